// round 1
// baseline (speedup 1.0000x reference)
#include <cuda_runtime.h>
#include <cuda_bf16.h>

#define N_NODES_MAX 100000
#define E_MAX       1600000
#define FDIM        128

// ---------------- scratch (device globals; no allocations allowed) ----------
__device__ float g_h[N_NODES_MAX * FDIM];    // GEMM output  (51.2 MB)
__device__ float g_buf[N_NODES_MAX * FDIM];  // aggregation output (51.2 MB)
__device__ float g_deg[N_NODES_MAX];
__device__ float g_dis[N_NODES_MAX];         // rsqrt(deg)
__device__ float g_norm[E_MAX];              // per-edge symmetric norm

// ---------------- preprocessing ---------------------------------------------
__global__ void init_deg_kernel(float* deg, int n) {
    int i = blockIdx.x * blockDim.x + threadIdx.x;
    if (i < n) deg[i] = 1.0f;  // self-loop
}

__global__ void deg_scatter_kernel(const int* __restrict__ dst, float* deg, int E) {
    int e = blockIdx.x * blockDim.x + threadIdx.x;
    if (e < E) atomicAdd(&deg[dst[e]], 1.0f);
}

__global__ void dis_kernel(const float* __restrict__ deg, float* dis, int n) {
    int i = blockIdx.x * blockDim.x + threadIdx.x;
    if (i < n) dis[i] = rsqrtf(deg[i]);
}

__global__ void norm_kernel(const int* __restrict__ src, const int* __restrict__ dst,
                            const float* __restrict__ dis, float* norm, int E) {
    int e = blockIdx.x * blockDim.x + threadIdx.x;
    if (e < E) norm[e] = dis[src[e]] * dis[dst[e]];
}

// ---------------- GEMM: out[M,BN] = (relu?)(A[M,128]) @ W[128,BN] -----------
template <int BN, bool RELU>
__global__ void gemm_kernel(const float* __restrict__ A, const float* __restrict__ W,
                            float* __restrict__ out, int M) {
    constexpr int K = 128, BM = 64, TN = BN / 16;
    constexpr int AS_STRIDE = K + 4;
    extern __shared__ float smem[];
    float* As = smem;                    // [BM][AS_STRIDE]
    float* Ws = smem + BM * AS_STRIDE;   // [K][BN]

    const int t = threadIdx.x;
    const int block_row = blockIdx.x * BM;

    for (int i = t * 4; i < K * BN; i += 256 * 4) {
        *reinterpret_cast<float4*>(Ws + i) = *reinterpret_cast<const float4*>(W + i);
    }
    for (int i = t * 4; i < BM * K; i += 256 * 4) {
        int r = i >> 7;
        int c = i & 127;
        int row = block_row + r;
        float4 v = make_float4(0.f, 0.f, 0.f, 0.f);
        if (row < M) v = *reinterpret_cast<const float4*>(A + (size_t)row * K + c);
        if (RELU) {
            v.x = fmaxf(v.x, 0.f); v.y = fmaxf(v.y, 0.f);
            v.z = fmaxf(v.z, 0.f); v.w = fmaxf(v.w, 0.f);
        }
        *reinterpret_cast<float4*>(As + r * AS_STRIDE + c) = v;
    }
    __syncthreads();

    const int tx = threadIdx.x & 15;
    const int ty = threadIdx.x >> 4;
    float acc[4][TN];
#pragma unroll
    for (int i = 0; i < 4; i++)
#pragma unroll
        for (int j = 0; j < TN; j++) acc[i][j] = 0.f;

    const float* a_base = As + (ty * 4) * AS_STRIDE;
    const float* w_base = Ws + tx * TN;

#pragma unroll 4
    for (int k = 0; k < K; ++k) {
        float a0 = a_base[k];
        float a1 = a_base[AS_STRIDE + k];
        float a2 = a_base[2 * AS_STRIDE + k];
        float a3 = a_base[3 * AS_STRIDE + k];
#pragma unroll
        for (int j4 = 0; j4 < TN; j4 += 4) {
            float4 w = *reinterpret_cast<const float4*>(w_base + k * BN + j4);
            acc[0][j4 + 0] += a0 * w.x; acc[0][j4 + 1] += a0 * w.y;
            acc[0][j4 + 2] += a0 * w.z; acc[0][j4 + 3] += a0 * w.w;
            acc[1][j4 + 0] += a1 * w.x; acc[1][j4 + 1] += a1 * w.y;
            acc[1][j4 + 2] += a1 * w.z; acc[1][j4 + 3] += a1 * w.w;
            acc[2][j4 + 0] += a2 * w.x; acc[2][j4 + 1] += a2 * w.y;
            acc[2][j4 + 2] += a2 * w.z; acc[2][j4 + 3] += a2 * w.w;
            acc[3][j4 + 0] += a3 * w.x; acc[3][j4 + 1] += a3 * w.y;
            acc[3][j4 + 2] += a3 * w.z; acc[3][j4 + 3] += a3 * w.w;
        }
    }

#pragma unroll
    for (int i = 0; i < 4; i++) {
        int row = block_row + ty * 4 + i;
        if (row < M) {
#pragma unroll
            for (int j4 = 0; j4 < TN; j4 += 4) {
                float4 v = make_float4(acc[i][j4], acc[i][j4 + 1], acc[i][j4 + 2], acc[i][j4 + 3]);
                *reinterpret_cast<float4*>(out + (size_t)row * BN + tx * TN + j4) = v;
            }
        }
    }
}

// ---------------- aggregation -----------------------------------------------
template <int NF>
__global__ void agg_init_kernel(const float* __restrict__ h, const float* __restrict__ b,
                                const float* __restrict__ dis, float* __restrict__ out, int n) {
    constexpr int PE = NF / 4;
    unsigned gid = blockIdx.x * blockDim.x + threadIdx.x;
    if (gid >= (unsigned)n * PE) return;
    int i = gid / PE;
    int c = (gid % PE) * 4;
    float d = dis[i];
    float sn = d * d;
    float4 hv = *reinterpret_cast<const float4*>(h + (size_t)i * NF + c);
    float4 bv = *reinterpret_cast<const float4*>(b + c);
    float4 o;
    o.x = bv.x + sn * hv.x; o.y = bv.y + sn * hv.y;
    o.z = bv.z + sn * hv.z; o.w = bv.w + sn * hv.w;
    *reinterpret_cast<float4*>(out + (size_t)i * NF + c) = o;
}

template <int NF>
__global__ void agg_scatter_kernel(const float* __restrict__ h, const int* __restrict__ src,
                                   const int* __restrict__ dst, const float* __restrict__ norm,
                                   float* __restrict__ out, int E) {
    constexpr int PE = NF / 4;
    unsigned gid = blockIdx.x * blockDim.x + threadIdx.x;
    if (gid >= (unsigned)E * PE) return;
    int e = gid / PE;
    int c = (gid % PE) * 4;
    int s = src[e];
    int d = dst[e];
    float nrm = norm[e];
    float4 v = *reinterpret_cast<const float4*>(h + (size_t)s * NF + c);
    float* p = out + (size_t)d * NF + c;
    asm volatile("red.global.add.v4.f32 [%0], {%1, %2, %3, %4};"
                 :: "l"(p), "f"(v.x * nrm), "f"(v.y * nrm), "f"(v.z * nrm), "f"(v.w * nrm)
                 : "memory");
}

// ---------------- epilogue: relu + log_softmax over 64 cols (stride 64) -----
__global__ void final_kernel(const float* __restrict__ hin, float* __restrict__ out, int n) {
    int warp = (blockIdx.x * blockDim.x + threadIdx.x) >> 5;
    int lane = threadIdx.x & 31;
    if (warp >= n) return;
    const float* row = hin + (size_t)warp * 64;
    float v0 = fmaxf(row[lane], 0.f);
    float v1 = fmaxf(row[32 + lane], 0.f);
    float m = fmaxf(v0, v1);
#pragma unroll
    for (int o = 16; o > 0; o >>= 1) m = fmaxf(m, __shfl_xor_sync(0xffffffffu, m, o));
    float s = __expf(v0 - m) + __expf(v1 - m);
#pragma unroll
    for (int o = 16; o > 0; o >>= 1) s += __shfl_xor_sync(0xffffffffu, s, o);
    float l = m + __logf(s);
    float* orow = out + (size_t)warp * 64;
    orow[lane] = v0 - l;
    orow[32 + lane] = v1 - l;
}

// ---------------- launch ----------------------------------------------------
extern "C" void kernel_launch(void* const* d_in, const int* in_sizes, int n_in,
                              void* d_out, int out_size) {
    const float* x  = (const float*)d_in[0];
    const int*   ei = (const int*)d_in[1];
    const float* W0 = (const float*)d_in[2];
    const float* b0 = (const float*)d_in[3];
    const float* W1 = (const float*)d_in[4];
    const float* b1 = (const float*)d_in[5];
    const float* W2 = (const float*)d_in[6];
    const float* b2 = (const float*)d_in[7];

    const int N = in_sizes[0] / FDIM;
    const int E = in_sizes[1] / 2;
    const int* src = ei;
    const int* dst = ei + E;

    float *h, *buf, *deg, *dis, *norm;
    cudaGetSymbolAddress((void**)&h, g_h);
    cudaGetSymbolAddress((void**)&buf, g_buf);
    cudaGetSymbolAddress((void**)&deg, g_deg);
    cudaGetSymbolAddress((void**)&dis, g_dis);
    cudaGetSymbolAddress((void**)&norm, g_norm);

    const int AS_BYTES = 64 * (128 + 4) * 4;
    const int smem128 = AS_BYTES + 128 * 128 * 4;  // 99328
    const int smem64  = AS_BYTES + 128 * 64 * 4;   // 66560
    cudaFuncSetAttribute((const void*)gemm_kernel<128, false>,
                         cudaFuncAttributeMaxDynamicSharedMemorySize, smem128);
    cudaFuncSetAttribute((const void*)gemm_kernel<128, true>,
                         cudaFuncAttributeMaxDynamicSharedMemorySize, smem128);
    cudaFuncSetAttribute((const void*)gemm_kernel<64, true>,
                         cudaFuncAttributeMaxDynamicSharedMemorySize, smem64);

    const int T = 256;
    auto cdiv = [](long long a, long long b) { return (unsigned)((a + b - 1) / b); };

    init_deg_kernel<<<cdiv(N, T), T>>>(deg, N);
    deg_scatter_kernel<<<cdiv(E, T), T>>>(dst, deg, E);
    dis_kernel<<<cdiv(N, T), T>>>(deg, dis, N);
    norm_kernel<<<cdiv(E, T), T>>>(src, dst, dis, norm, E);

    const unsigned gemm_grid = cdiv(N, 64);

    // layer 0
    gemm_kernel<128, false><<<gemm_grid, T, smem128>>>(x, W0, h, N);
    agg_init_kernel<128><<<cdiv((long long)N * 32, T), T>>>(h, b0, dis, buf, N);
    agg_scatter_kernel<128><<<cdiv((long long)E * 32, T), T>>>(h, src, dst, norm, buf, E);

    // layer 1 (relu fused into GEMM A-load)
    gemm_kernel<128, true><<<gemm_grid, T, smem128>>>(buf, W1, h, N);
    agg_init_kernel<128><<<cdiv((long long)N * 32, T), T>>>(h, b1, dis, buf, N);
    agg_scatter_kernel<128><<<cdiv((long long)E * 32, T), T>>>(h, src, dst, norm, buf, E);

    // layer 2 (64 out dims, stride 64 in h/buf)
    gemm_kernel<64, true><<<gemm_grid, T, smem64>>>(buf, W2, h, N);
    agg_init_kernel<64><<<cdiv((long long)N * 16, T), T>>>(h, b2, dis, buf, N);
    agg_scatter_kernel<64><<<cdiv((long long)E * 16, T), T>>>(h, src, dst, norm, buf, E);

    // relu + log_softmax -> d_out
    final_kernel<<<cdiv((long long)N * 32, T), T>>>(buf, (float*)d_out, N);
}

// round 3
// speedup vs baseline: 1.5294x; 1.5294x over previous
#include <cuda_runtime.h>
#include <cuda_bf16.h>

#define N_NODES_MAX 100000
#define E_MAX       1600000
#define FDIM        128
#define SCAN_B      1024

// ---------------- scratch (device globals; no allocations allowed) ----------
__device__ float g_h[N_NODES_MAX * FDIM];    // GEMM output  (51.2 MB)
__device__ float g_buf[N_NODES_MAX * FDIM];  // aggregation output (51.2 MB)
__device__ float g_dis[N_NODES_MAX];         // rsqrt(deg)
__device__ int   g_cnt[N_NODES_MAX];         // in-degree (no self-loop)
__device__ int   g_rowptr[N_NODES_MAX];      // exclusive-scan of cnt
__device__ int   g_cursor[N_NODES_MAX];      // permute cursors
__device__ int   g_bsum[(N_NODES_MAX + SCAN_B - 1) / SCAN_B + 1];
__device__ int   g_csr_src[E_MAX];
__device__ float g_csr_norm[E_MAX];

// ---------------- CSR build --------------------------------------------------
__global__ void zero_cnt_kernel(int* cnt, int n) {
    int i = blockIdx.x * blockDim.x + threadIdx.x;
    if (i < n) cnt[i] = 0;
}

__global__ void hist_kernel(const int* __restrict__ dst, int* cnt, int E) {
    int e = blockIdx.x * blockDim.x + threadIdx.x;
    if (e < E) atomicAdd(&cnt[dst[e]], 1);
}

__global__ void dis_kernel(const int* __restrict__ cnt, float* dis, int n) {
    int i = blockIdx.x * blockDim.x + threadIdx.x;
    if (i < n) dis[i] = rsqrtf((float)(cnt[i] + 1));  // +1 self-loop
}

// block-level exclusive scan (Hillis-Steele in smem), emit block sums
__global__ void scan1_kernel(const int* __restrict__ cnt, int* rowptr, int* bsum, int n) {
    __shared__ int sh[SCAN_B];
    int gid = blockIdx.x * SCAN_B + threadIdx.x;
    int v = (gid < n) ? cnt[gid] : 0;
    sh[threadIdx.x] = v;
    __syncthreads();
#pragma unroll
    for (int off = 1; off < SCAN_B; off <<= 1) {
        int t = (threadIdx.x >= off) ? sh[threadIdx.x - off] : 0;
        __syncthreads();
        sh[threadIdx.x] += t;
        __syncthreads();
    }
    if (gid < n) rowptr[gid] = sh[threadIdx.x] - v;  // exclusive
    if (threadIdx.x == SCAN_B - 1) bsum[blockIdx.x] = sh[SCAN_B - 1];
}

// single-block exclusive scan over block sums (nb <= 1024)
__global__ void scan2_kernel(int* bsum, int nb) {
    __shared__ int sh[SCAN_B];
    int v = (threadIdx.x < nb) ? bsum[threadIdx.x] : 0;
    sh[threadIdx.x] = v;
    __syncthreads();
#pragma unroll
    for (int off = 1; off < SCAN_B; off <<= 1) {
        int t = (threadIdx.x >= off) ? sh[threadIdx.x - off] : 0;
        __syncthreads();
        sh[threadIdx.x] += t;
        __syncthreads();
    }
    if (threadIdx.x < nb) bsum[threadIdx.x] = sh[threadIdx.x] - v;
}

// add block offsets; also init cursor = rowptr
__global__ void scan3_kernel(int* rowptr, int* cursor, const int* __restrict__ bsum, int n) {
    int gid = blockIdx.x * blockDim.x + threadIdx.x;
    if (gid < n) {
        int r = rowptr[gid] + bsum[gid / SCAN_B];
        rowptr[gid] = r;
        cursor[gid] = r;
    }
}

__global__ void permute_kernel(const int* __restrict__ src, const int* __restrict__ dst,
                               const float* __restrict__ dis, int* cursor,
                               int* csr_src, float* csr_norm, int E) {
    int e = blockIdx.x * blockDim.x + threadIdx.x;
    if (e < E) {
        int s = src[e], d = dst[e];
        int pos = atomicAdd(&cursor[d], 1);
        csr_src[pos] = s;
        csr_norm[pos] = dis[s] * dis[d];
    }
}

// ---------------- GEMM: out[M,BN] = (relu?)(A[M,128]) @ W[128,BN] -----------
template <int BN, bool RELU>
__global__ void gemm_kernel(const float* __restrict__ A, const float* __restrict__ W,
                            float* __restrict__ out, int M) {
    constexpr int K = 128, BM = 64, TN = BN / 16;
    constexpr int AS_STRIDE = K + 4;
    extern __shared__ float smem[];
    float* As = smem;                    // [BM][AS_STRIDE]
    float* Ws = smem + BM * AS_STRIDE;   // [K][BN]

    const int t = threadIdx.x;
    const int block_row = blockIdx.x * BM;

    for (int i = t * 4; i < K * BN; i += 256 * 4) {
        *reinterpret_cast<float4*>(Ws + i) = *reinterpret_cast<const float4*>(W + i);
    }
    for (int i = t * 4; i < BM * K; i += 256 * 4) {
        int r = i >> 7;
        int c = i & 127;
        int row = block_row + r;
        float4 v = make_float4(0.f, 0.f, 0.f, 0.f);
        if (row < M) v = *reinterpret_cast<const float4*>(A + (size_t)row * K + c);
        if (RELU) {
            v.x = fmaxf(v.x, 0.f); v.y = fmaxf(v.y, 0.f);
            v.z = fmaxf(v.z, 0.f); v.w = fmaxf(v.w, 0.f);
        }
        *reinterpret_cast<float4*>(As + r * AS_STRIDE + c) = v;
    }
    __syncthreads();

    const int tx = threadIdx.x & 15;
    const int ty = threadIdx.x >> 4;
    float acc[4][TN];
#pragma unroll
    for (int i = 0; i < 4; i++)
#pragma unroll
        for (int j = 0; j < TN; j++) acc[i][j] = 0.f;

    const float* a_base = As + (ty * 4) * AS_STRIDE;
    const float* w_base = Ws + tx * TN;

#pragma unroll 4
    for (int k = 0; k < K; ++k) {
        float a0 = a_base[k];
        float a1 = a_base[AS_STRIDE + k];
        float a2 = a_base[2 * AS_STRIDE + k];
        float a3 = a_base[3 * AS_STRIDE + k];
#pragma unroll
        for (int j4 = 0; j4 < TN; j4 += 4) {
            float4 w = *reinterpret_cast<const float4*>(w_base + k * BN + j4);
            acc[0][j4 + 0] += a0 * w.x; acc[0][j4 + 1] += a0 * w.y;
            acc[0][j4 + 2] += a0 * w.z; acc[0][j4 + 3] += a0 * w.w;
            acc[1][j4 + 0] += a1 * w.x; acc[1][j4 + 1] += a1 * w.y;
            acc[1][j4 + 2] += a1 * w.z; acc[1][j4 + 3] += a1 * w.w;
            acc[2][j4 + 0] += a2 * w.x; acc[2][j4 + 1] += a2 * w.y;
            acc[2][j4 + 2] += a2 * w.z; acc[2][j4 + 3] += a2 * w.w;
            acc[3][j4 + 0] += a3 * w.x; acc[3][j4 + 1] += a3 * w.y;
            acc[3][j4 + 2] += a3 * w.z; acc[3][j4 + 3] += a3 * w.w;
        }
    }

#pragma unroll
    for (int i = 0; i < 4; i++) {
        int row = block_row + ty * 4 + i;
        if (row < M) {
#pragma unroll
            for (int j4 = 0; j4 < TN; j4 += 4) {
                float4 v = make_float4(acc[i][j4], acc[i][j4 + 1], acc[i][j4 + 2], acc[i][j4 + 3]);
                *reinterpret_cast<float4*>(out + (size_t)row * BN + tx * TN + j4) = v;
            }
        }
    }
}

// ---------------- aggregation: warp-per-node CSR gather ---------------------
// out[v] = b + dis[v]^2 * h[v] + sum_e norm_e * h[csr_src[e]]
__global__ void agg_gather128_kernel(const float* __restrict__ h,
                                     const int* __restrict__ rowptr,
                                     const int* __restrict__ cnt,
                                     const int* __restrict__ csr_src,
                                     const float* __restrict__ csr_norm,
                                     const float* __restrict__ b,
                                     const float* __restrict__ dis,
                                     float* __restrict__ out, int n) {
    int warp = (blockIdx.x * blockDim.x + threadIdx.x) >> 5;
    int lane = threadIdx.x & 31;
    if (warp >= n) return;
    const int v = warp;
    const int c = lane * 4;

    float d = dis[v];
    float sn = d * d;
    float4 acc = *reinterpret_cast<const float4*>(b + c);
    float4 hv = *reinterpret_cast<const float4*>(h + (size_t)v * 128 + c);
    acc.x += sn * hv.x; acc.y += sn * hv.y; acc.z += sn * hv.z; acc.w += sn * hv.w;

    int j = rowptr[v];
    const int end = j + cnt[v];
    for (; j + 4 <= end; j += 4) {
        int s0 = csr_src[j], s1 = csr_src[j + 1], s2 = csr_src[j + 2], s3 = csr_src[j + 3];
        float n0 = csr_norm[j], n1 = csr_norm[j + 1], n2 = csr_norm[j + 2], n3 = csr_norm[j + 3];
        float4 v0 = *reinterpret_cast<const float4*>(h + (size_t)s0 * 128 + c);
        float4 v1 = *reinterpret_cast<const float4*>(h + (size_t)s1 * 128 + c);
        float4 v2 = *reinterpret_cast<const float4*>(h + (size_t)s2 * 128 + c);
        float4 v3 = *reinterpret_cast<const float4*>(h + (size_t)s3 * 128 + c);
        acc.x += n0 * v0.x + n1 * v1.x + n2 * v2.x + n3 * v3.x;
        acc.y += n0 * v0.y + n1 * v1.y + n2 * v2.y + n3 * v3.y;
        acc.z += n0 * v0.z + n1 * v1.z + n2 * v2.z + n3 * v3.z;
        acc.w += n0 * v0.w + n1 * v1.w + n2 * v2.w + n3 * v3.w;
    }
    for (; j < end; ++j) {
        int s = csr_src[j];
        float nn = csr_norm[j];
        float4 vv = *reinterpret_cast<const float4*>(h + (size_t)s * 128 + c);
        acc.x += nn * vv.x; acc.y += nn * vv.y; acc.z += nn * vv.z; acc.w += nn * vv.w;
    }
    *reinterpret_cast<float4*>(out + (size_t)v * 128 + c) = acc;
}

// 64-dim variant: lane holds float2
__global__ void agg_gather64_kernel(const float* __restrict__ h,
                                    const int* __restrict__ rowptr,
                                    const int* __restrict__ cnt,
                                    const int* __restrict__ csr_src,
                                    const float* __restrict__ csr_norm,
                                    const float* __restrict__ b,
                                    const float* __restrict__ dis,
                                    float* __restrict__ out, int n) {
    int warp = (blockIdx.x * blockDim.x + threadIdx.x) >> 5;
    int lane = threadIdx.x & 31;
    if (warp >= n) return;
    const int v = warp;
    const int c = lane * 2;

    float d = dis[v];
    float sn = d * d;
    float2 acc = *reinterpret_cast<const float2*>(b + c);
    float2 hv = *reinterpret_cast<const float2*>(h + (size_t)v * 64 + c);
    acc.x += sn * hv.x; acc.y += sn * hv.y;

    int j = rowptr[v];
    const int end = j + cnt[v];
    for (; j + 4 <= end; j += 4) {
        int s0 = csr_src[j], s1 = csr_src[j + 1], s2 = csr_src[j + 2], s3 = csr_src[j + 3];
        float n0 = csr_norm[j], n1 = csr_norm[j + 1], n2 = csr_norm[j + 2], n3 = csr_norm[j + 3];
        float2 v0 = *reinterpret_cast<const float2*>(h + (size_t)s0 * 64 + c);
        float2 v1 = *reinterpret_cast<const float2*>(h + (size_t)s1 * 64 + c);
        float2 v2 = *reinterpret_cast<const float2*>(h + (size_t)s2 * 64 + c);
        float2 v3 = *reinterpret_cast<const float2*>(h + (size_t)s3 * 64 + c);
        acc.x += n0 * v0.x + n1 * v1.x + n2 * v2.x + n3 * v3.x;
        acc.y += n0 * v0.y + n1 * v1.y + n2 * v2.y + n3 * v3.y;
    }
    for (; j < end; ++j) {
        int s = csr_src[j];
        float nn = csr_norm[j];
        float2 vv = *reinterpret_cast<const float2*>(h + (size_t)s * 64 + c);
        acc.x += nn * vv.x; acc.y += nn * vv.y;
    }
    *reinterpret_cast<float2*>(out + (size_t)v * 64 + c) = acc;
}

// ---------------- epilogue: relu + log_softmax over 64 cols (stride 64) -----
__global__ void final_kernel(const float* __restrict__ hin, float* __restrict__ out, int n) {
    int warp = (blockIdx.x * blockDim.x + threadIdx.x) >> 5;
    int lane = threadIdx.x & 31;
    if (warp >= n) return;
    const float* row = hin + (size_t)warp * 64;
    float v0 = fmaxf(row[lane], 0.f);
    float v1 = fmaxf(row[32 + lane], 0.f);
    float m = fmaxf(v0, v1);
#pragma unroll
    for (int o = 16; o > 0; o >>= 1) m = fmaxf(m, __shfl_xor_sync(0xffffffffu, m, o));
    float s = __expf(v0 - m) + __expf(v1 - m);
#pragma unroll
    for (int o = 16; o > 0; o >>= 1) s += __shfl_xor_sync(0xffffffffu, s, o);
    float l = m + __logf(s);
    float* orow = out + (size_t)warp * 64;
    orow[lane] = v0 - l;
    orow[32 + lane] = v1 - l;
}

// ---------------- launch ----------------------------------------------------
extern "C" void kernel_launch(void* const* d_in, const int* in_sizes, int n_in,
                              void* d_out, int out_size) {
    const float* x  = (const float*)d_in[0];
    const int*   ei = (const int*)d_in[1];
    const float* W0 = (const float*)d_in[2];
    const float* b0 = (const float*)d_in[3];
    const float* W1 = (const float*)d_in[4];
    const float* b1 = (const float*)d_in[5];
    const float* W2 = (const float*)d_in[6];
    const float* b2 = (const float*)d_in[7];

    const int N = in_sizes[0] / FDIM;
    const int E = in_sizes[1] / 2;
    const int* src = ei;
    const int* dst = ei + E;

    float *h, *buf, *dis, *csr_norm;
    int *cnt, *rowptr, *cursor, *bsum, *csr_src;
    cudaGetSymbolAddress((void**)&h, g_h);
    cudaGetSymbolAddress((void**)&buf, g_buf);
    cudaGetSymbolAddress((void**)&dis, g_dis);
    cudaGetSymbolAddress((void**)&cnt, g_cnt);
    cudaGetSymbolAddress((void**)&rowptr, g_rowptr);
    cudaGetSymbolAddress((void**)&cursor, g_cursor);
    cudaGetSymbolAddress((void**)&bsum, g_bsum);
    cudaGetSymbolAddress((void**)&csr_src, g_csr_src);
    cudaGetSymbolAddress((void**)&csr_norm, g_csr_norm);

    const int AS_BYTES = 64 * (128 + 4) * 4;
    const int smem128 = AS_BYTES + 128 * 128 * 4;  // 99328
    const int smem64  = AS_BYTES + 128 * 64 * 4;   // 66560
    cudaFuncSetAttribute((const void*)gemm_kernel<128, false>,
                         cudaFuncAttributeMaxDynamicSharedMemorySize, smem128);
    cudaFuncSetAttribute((const void*)gemm_kernel<128, true>,
                         cudaFuncAttributeMaxDynamicSharedMemorySize, smem128);
    cudaFuncSetAttribute((const void*)gemm_kernel<64, true>,
                         cudaFuncAttributeMaxDynamicSharedMemorySize, smem64);

    const int T = 256;
    auto cdiv = [](long long a, long long b) { return (unsigned)((a + b - 1) / b); };
    const int nb = (int)cdiv(N, SCAN_B);

    // ---- CSR build (also produces deg/dis/norm) ----
    zero_cnt_kernel<<<cdiv(N, T), T>>>(cnt, N);
    hist_kernel<<<cdiv(E, T), T>>>(dst, cnt, E);
    dis_kernel<<<cdiv(N, T), T>>>(cnt, dis, N);
    scan1_kernel<<<nb, SCAN_B>>>(cnt, rowptr, bsum, N);
    scan2_kernel<<<1, SCAN_B>>>(bsum, nb);
    scan3_kernel<<<cdiv(N, T), T>>>(rowptr, cursor, bsum, N);
    permute_kernel<<<cdiv(E, T), T>>>(src, dst, dis, cursor, csr_src, csr_norm, E);

    const unsigned gemm_grid = cdiv(N, 64);
    const unsigned warp_grid = cdiv((long long)N * 32, T);

    // layer 0
    gemm_kernel<128, false><<<gemm_grid, T, smem128>>>(x, W0, h, N);
    agg_gather128_kernel<<<warp_grid, T>>>(h, rowptr, cnt, csr_src, csr_norm, b0, dis, buf, N);

    // layer 1 (relu fused into GEMM A-load)
    gemm_kernel<128, true><<<gemm_grid, T, smem128>>>(buf, W1, h, N);
    agg_gather128_kernel<<<warp_grid, T>>>(h, rowptr, cnt, csr_src, csr_norm, b1, dis, buf, N);

    // layer 2 (64 out dims, stride 64 in h/buf)
    gemm_kernel<64, true><<<gemm_grid, T, smem64>>>(buf, W2, h, N);
    agg_gather64_kernel<<<warp_grid, T>>>(h, rowptr, cnt, csr_src, csr_norm, b2, dis, buf, N);

    // relu + log_softmax -> d_out
    final_kernel<<<warp_grid, T>>>(buf, (float*)d_out, N);
}

// round 5
// speedup vs baseline: 2.2000x; 1.4385x over previous
#include <cuda_runtime.h>
#include <cuda_bf16.h>
#include <cstdint>

#define N_NODES_MAX 100000
#define E_MAX       1600000
#define FDIM        128
#define SCAN_B      1024

// ---------------- scratch (device globals; no allocations allowed) ----------
__device__ float g_h[N_NODES_MAX * FDIM];    // GEMM output  (51.2 MB)
__device__ float g_buf[N_NODES_MAX * FDIM];  // aggregation output (51.2 MB)
__device__ float g_dis[N_NODES_MAX];         // rsqrt(deg)
__device__ int   g_cnt[N_NODES_MAX];         // in-degree (no self-loop)
__device__ int   g_rowptr[N_NODES_MAX];      // exclusive-scan of cnt
__device__ int   g_cursor[N_NODES_MAX];      // permute cursors
__device__ int   g_bsum[(N_NODES_MAX + SCAN_B - 1) / SCAN_B + 1];
__device__ int   g_csr_src[E_MAX];
__device__ float g_csr_norm[E_MAX];

// ---------------- CSR build --------------------------------------------------
__global__ void zero_cnt_kernel(int* cnt, int n) {
    int i = blockIdx.x * blockDim.x + threadIdx.x;
    if (i < n) cnt[i] = 0;
}

__global__ void hist_kernel(const int* __restrict__ dst, int* cnt, int E) {
    int e = blockIdx.x * blockDim.x + threadIdx.x;
    if (e < E) atomicAdd(&cnt[dst[e]], 1);
}

__global__ void dis_kernel(const int* __restrict__ cnt, float* dis, int n) {
    int i = blockIdx.x * blockDim.x + threadIdx.x;
    if (i < n) dis[i] = rsqrtf((float)(cnt[i] + 1));  // +1 self-loop
}

__global__ void scan1_kernel(const int* __restrict__ cnt, int* rowptr, int* bsum, int n) {
    __shared__ int sh[SCAN_B];
    int gid = blockIdx.x * SCAN_B + threadIdx.x;
    int v = (gid < n) ? cnt[gid] : 0;
    sh[threadIdx.x] = v;
    __syncthreads();
#pragma unroll
    for (int off = 1; off < SCAN_B; off <<= 1) {
        int t = (threadIdx.x >= off) ? sh[threadIdx.x - off] : 0;
        __syncthreads();
        sh[threadIdx.x] += t;
        __syncthreads();
    }
    if (gid < n) rowptr[gid] = sh[threadIdx.x] - v;  // exclusive
    if (threadIdx.x == SCAN_B - 1) bsum[blockIdx.x] = sh[SCAN_B - 1];
}

__global__ void scan2_kernel(int* bsum, int nb) {
    __shared__ int sh[SCAN_B];
    int v = (threadIdx.x < nb) ? bsum[threadIdx.x] : 0;
    sh[threadIdx.x] = v;
    __syncthreads();
#pragma unroll
    for (int off = 1; off < SCAN_B; off <<= 1) {
        int t = (threadIdx.x >= off) ? sh[threadIdx.x - off] : 0;
        __syncthreads();
        sh[threadIdx.x] += t;
        __syncthreads();
    }
    if (threadIdx.x < nb) bsum[threadIdx.x] = sh[threadIdx.x] - v;
}

__global__ void scan3_kernel(int* rowptr, int* cursor, const int* __restrict__ bsum, int n) {
    int gid = blockIdx.x * blockDim.x + threadIdx.x;
    if (gid < n) {
        int r = rowptr[gid] + bsum[gid / SCAN_B];
        rowptr[gid] = r;
        cursor[gid] = r;
    }
}

__global__ void permute_kernel(const int* __restrict__ src, const int* __restrict__ dst,
                               const float* __restrict__ dis, int* cursor,
                               int* csr_src, float* csr_norm, int E) {
    int e = blockIdx.x * blockDim.x + threadIdx.x;
    if (e < E) {
        int s = src[e], d = dst[e];
        int pos = atomicAdd(&cursor[d], 1);
        csr_src[pos] = s;
        csr_norm[pos] = dis[s] * dis[d];
    }
}

// ---------------- tensor-core GEMM (bf16x2 split, mma.sync) -----------------
__device__ __forceinline__ uint32_t pack_bf16x2(__nv_bfloat16 e0, __nv_bfloat16 e1) {
    return ((uint32_t)__bfloat16_as_ushort(e1) << 16) | (uint32_t)__bfloat16_as_ushort(e0);
}

__device__ __forceinline__ void split_store4(float4 v, __nv_bfloat16* ph, __nv_bfloat16* pl) {
    __nv_bfloat16 h0 = __float2bfloat16(v.x);
    __nv_bfloat16 h1 = __float2bfloat16(v.y);
    __nv_bfloat16 h2 = __float2bfloat16(v.z);
    __nv_bfloat16 h3 = __float2bfloat16(v.w);
    __nv_bfloat16 l0 = __float2bfloat16(v.x - __bfloat162float(h0));
    __nv_bfloat16 l1 = __float2bfloat16(v.y - __bfloat162float(h1));
    __nv_bfloat16 l2 = __float2bfloat16(v.z - __bfloat162float(h2));
    __nv_bfloat16 l3 = __float2bfloat16(v.w - __bfloat162float(h3));
    uint2 uh = make_uint2(pack_bf16x2(h0, h1), pack_bf16x2(h2, h3));
    uint2 ul = make_uint2(pack_bf16x2(l0, l1), pack_bf16x2(l2, l3));
    *reinterpret_cast<uint2*>(ph) = uh;
    *reinterpret_cast<uint2*>(pl) = ul;
}

#define MMA_BF16(acc, a, b)                                                              \
    asm volatile(                                                                        \
        "mma.sync.aligned.m16n8k16.row.col.f32.bf16.bf16.f32 "                           \
        "{%0,%1,%2,%3}, {%4,%5,%6,%7}, {%8,%9}, {%0,%1,%2,%3};"                          \
        : "+f"((acc)[0]), "+f"((acc)[1]), "+f"((acc)[2]), "+f"((acc)[3])                 \
        : "r"((a)[0]), "r"((a)[1]), "r"((a)[2]), "r"((a)[3]), "r"((b)[0]), "r"((b)[1]))

// out[M,BN] = (relu?)(A[M,128]) @ W[128,BN]; D = Ah@Wh + Ah@Wl + Al@Wh
template <int BN, bool RELU>
__global__ __launch_bounds__(256) void gemm_tc_kernel(const float* __restrict__ A,
                                                      const float* __restrict__ W,
                                                      float* __restrict__ out, int M) {
    constexpr int K = 128;
    constexpr int NWN = BN / 32;   // warps along N (4 or 2)
    constexpr int NWM = 8 / NWN;   // warps along M (2 or 4)
    constexpr int BM = NWM * 32;   // 64 or 128
    constexpr int KP = K + 8;      // A smem row stride (bf16) -> 272B, bank-shift 4
    constexpr int NP = BN + 8;     // W smem row stride

    extern __shared__ __nv_bfloat16 smb[];
    __nv_bfloat16* Ah = smb;                 // [BM][KP]
    __nv_bfloat16* Al = Ah + BM * KP;
    __nv_bfloat16* Wh = Al + BM * KP;        // [K][NP]
    __nv_bfloat16* Wl = Wh + K * NP;

    const int t = threadIdx.x;
    const int block_row = blockIdx.x * BM;

    // stage W (hi/lo), row-major
    for (int i = t * 4; i < K * BN; i += 1024) {
        const int k = i / BN, n = i % BN;
        float4 v = *reinterpret_cast<const float4*>(W + i);
        split_store4(v, Wh + k * NP + n, Wl + k * NP + n);
    }
    // stage A (hi/lo), optional relu, zero-pad OOB rows
    for (int i = t * 4; i < BM * K; i += 1024) {
        const int r = i >> 7, c = i & 127;
        const int row = block_row + r;
        float4 v = make_float4(0.f, 0.f, 0.f, 0.f);
        if (row < M) v = *reinterpret_cast<const float4*>(A + (size_t)row * K + c);
        if (RELU) {
            v.x = fmaxf(v.x, 0.f); v.y = fmaxf(v.y, 0.f);
            v.z = fmaxf(v.z, 0.f); v.w = fmaxf(v.w, 0.f);
        }
        split_store4(v, Ah + r * KP + c, Al + r * KP + c);
    }
    __syncthreads();

    const int w = t >> 5, l = t & 31;
    const int wm = w / NWN, wn = w % NWN;   // warp tile = 32x32
    const int g = l >> 2, tq = l & 3;

    float acc[2][4][4];
#pragma unroll
    for (int mi = 0; mi < 2; mi++)
#pragma unroll
        for (int ni = 0; ni < 4; ni++)
#pragma unroll
            for (int r = 0; r < 4; r++) acc[mi][ni][r] = 0.f;

    // per-lane element offsets (bf16 units)
    const int a_row0 = wm * 32 + g;          // + mi*16 (+8 for a1/a3)
    const int b_row  = l & 15;               // ldmatrix source row within k-step
    const int b_col  = wn * 32;              // + ni*8

#pragma unroll
    for (int kk = 0; kk < 8; kk++) {
        const int k0 = kk * 16;
        uint32_t ah[2][4], al_[2][4];
#pragma unroll
        for (int mi = 0; mi < 2; mi++) {
            const int rb = (a_row0 + mi * 16) * KP + k0 + 2 * tq;
            ah[mi][0]  = *reinterpret_cast<const uint32_t*>(Ah + rb);
            ah[mi][1]  = *reinterpret_cast<const uint32_t*>(Ah + rb + 8 * KP);
            ah[mi][2]  = *reinterpret_cast<const uint32_t*>(Ah + rb + 8);
            ah[mi][3]  = *reinterpret_cast<const uint32_t*>(Ah + rb + 8 * KP + 8);
            al_[mi][0] = *reinterpret_cast<const uint32_t*>(Al + rb);
            al_[mi][1] = *reinterpret_cast<const uint32_t*>(Al + rb + 8 * KP);
            al_[mi][2] = *reinterpret_cast<const uint32_t*>(Al + rb + 8);
            al_[mi][3] = *reinterpret_cast<const uint32_t*>(Al + rb + 8 * KP + 8);
        }
        uint32_t bh[4][2], bl[4][2];
#pragma unroll
        for (int ni = 0; ni < 4; ni++) {
            const int off = (k0 + b_row) * NP + b_col + ni * 8;
            uint32_t ph = (uint32_t)__cvta_generic_to_shared(Wh + off);
            uint32_t pl = (uint32_t)__cvta_generic_to_shared(Wl + off);
            asm volatile("ldmatrix.sync.aligned.m8n8.x2.trans.shared.b16 {%0,%1}, [%2];"
                         : "=r"(bh[ni][0]), "=r"(bh[ni][1]) : "r"(ph));
            asm volatile("ldmatrix.sync.aligned.m8n8.x2.trans.shared.b16 {%0,%1}, [%2];"
                         : "=r"(bl[ni][0]), "=r"(bl[ni][1]) : "r"(pl));
        }
#pragma unroll
        for (int mi = 0; mi < 2; mi++)
#pragma unroll
            for (int ni = 0; ni < 4; ni++) {
                MMA_BF16(acc[mi][ni], ah[mi], bh[ni]);
                MMA_BF16(acc[mi][ni], ah[mi], bl[ni]);
                MMA_BF16(acc[mi][ni], al_[mi], bh[ni]);
            }
    }

    // epilogue: C fragment -> gmem (c0,c1)=(row g, col 2tq..), (c2,c3)=row g+8
#pragma unroll
    for (int mi = 0; mi < 2; mi++) {
#pragma unroll
        for (int ni = 0; ni < 4; ni++) {
            const int row = block_row + wm * 32 + mi * 16 + g;
            const int col = wn * 32 + ni * 8 + 2 * tq;
            if (row < M)
                *reinterpret_cast<float2*>(out + (size_t)row * BN + col) =
                    make_float2(acc[mi][ni][0], acc[mi][ni][1]);
            if (row + 8 < M)
                *reinterpret_cast<float2*>(out + (size_t)(row + 8) * BN + col) =
                    make_float2(acc[mi][ni][2], acc[mi][ni][3]);
        }
    }
}

// ---------------- aggregation: warp-per-node CSR gather ---------------------
__global__ void agg_gather128_kernel(const float* __restrict__ h,
                                     const int* __restrict__ rowptr,
                                     const int* __restrict__ cnt,
                                     const int* __restrict__ csr_src,
                                     const float* __restrict__ csr_norm,
                                     const float* __restrict__ b,
                                     const float* __restrict__ dis,
                                     float* __restrict__ out, int n) {
    int warp = (blockIdx.x * blockDim.x + threadIdx.x) >> 5;
    int lane = threadIdx.x & 31;
    if (warp >= n) return;
    const int v = warp;
    const int c = lane * 4;

    float d = dis[v];
    float sn = d * d;
    float4 acc = *reinterpret_cast<const float4*>(b + c);
    float4 hv = *reinterpret_cast<const float4*>(h + (size_t)v * 128 + c);
    acc.x += sn * hv.x; acc.y += sn * hv.y; acc.z += sn * hv.z; acc.w += sn * hv.w;

    int j = rowptr[v];
    const int end = j + cnt[v];
    for (; j + 4 <= end; j += 4) {
        int s0 = csr_src[j], s1 = csr_src[j + 1], s2 = csr_src[j + 2], s3 = csr_src[j + 3];
        float n0 = csr_norm[j], n1 = csr_norm[j + 1], n2 = csr_norm[j + 2], n3 = csr_norm[j + 3];
        float4 v0 = *reinterpret_cast<const float4*>(h + (size_t)s0 * 128 + c);
        float4 v1 = *reinterpret_cast<const float4*>(h + (size_t)s1 * 128 + c);
        float4 v2 = *reinterpret_cast<const float4*>(h + (size_t)s2 * 128 + c);
        float4 v3 = *reinterpret_cast<const float4*>(h + (size_t)s3 * 128 + c);
        acc.x += n0 * v0.x + n1 * v1.x + n2 * v2.x + n3 * v3.x;
        acc.y += n0 * v0.y + n1 * v1.y + n2 * v2.y + n3 * v3.y;
        acc.z += n0 * v0.z + n1 * v1.z + n2 * v2.z + n3 * v3.z;
        acc.w += n0 * v0.w + n1 * v1.w + n2 * v2.w + n3 * v3.w;
    }
    for (; j < end; ++j) {
        int s = csr_src[j];
        float nn = csr_norm[j];
        float4 vv = *reinterpret_cast<const float4*>(h + (size_t)s * 128 + c);
        acc.x += nn * vv.x; acc.y += nn * vv.y; acc.z += nn * vv.z; acc.w += nn * vv.w;
    }
    *reinterpret_cast<float4*>(out + (size_t)v * 128 + c) = acc;
}

__global__ void agg_gather64_kernel(const float* __restrict__ h,
                                    const int* __restrict__ rowptr,
                                    const int* __restrict__ cnt,
                                    const int* __restrict__ csr_src,
                                    const float* __restrict__ csr_norm,
                                    const float* __restrict__ b,
                                    const float* __restrict__ dis,
                                    float* __restrict__ out, int n) {
    int warp = (blockIdx.x * blockDim.x + threadIdx.x) >> 5;
    int lane = threadIdx.x & 31;
    if (warp >= n) return;
    const int v = warp;
    const int c = lane * 2;

    float d = dis[v];
    float sn = d * d;
    float2 acc = *reinterpret_cast<const float2*>(b + c);
    float2 hv = *reinterpret_cast<const float2*>(h + (size_t)v * 64 + c);
    acc.x += sn * hv.x; acc.y += sn * hv.y;

    int j = rowptr[v];
    const int end = j + cnt[v];
    for (; j + 4 <= end; j += 4) {
        int s0 = csr_src[j], s1 = csr_src[j + 1], s2 = csr_src[j + 2], s3 = csr_src[j + 3];
        float n0 = csr_norm[j], n1 = csr_norm[j + 1], n2 = csr_norm[j + 2], n3 = csr_norm[j + 3];
        float2 v0 = *reinterpret_cast<const float2*>(h + (size_t)s0 * 64 + c);
        float2 v1 = *reinterpret_cast<const float2*>(h + (size_t)s1 * 64 + c);
        float2 v2 = *reinterpret_cast<const float2*>(h + (size_t)s2 * 64 + c);
        float2 v3 = *reinterpret_cast<const float2*>(h + (size_t)s3 * 64 + c);
        acc.x += n0 * v0.x + n1 * v1.x + n2 * v2.x + n3 * v3.x;
        acc.y += n0 * v0.y + n1 * v1.y + n2 * v2.y + n3 * v3.y;
    }
    for (; j < end; ++j) {
        int s = csr_src[j];
        float nn = csr_norm[j];
        float2 vv = *reinterpret_cast<const float2*>(h + (size_t)s * 64 + c);
        acc.x += nn * vv.x; acc.y += nn * vv.y;
    }
    *reinterpret_cast<float2*>(out + (size_t)v * 64 + c) = acc;
}

// ---------------- epilogue: relu + log_softmax over 64 cols (stride 64) -----
__global__ void final_kernel(const float* __restrict__ hin, float* __restrict__ out, int n) {
    int warp = (blockIdx.x * blockDim.x + threadIdx.x) >> 5;
    int lane = threadIdx.x & 31;
    if (warp >= n) return;
    const float* row = hin + (size_t)warp * 64;
    float v0 = fmaxf(row[lane], 0.f);
    float v1 = fmaxf(row[32 + lane], 0.f);
    float m = fmaxf(v0, v1);
#pragma unroll
    for (int o = 16; o > 0; o >>= 1) m = fmaxf(m, __shfl_xor_sync(0xffffffffu, m, o));
    float s = __expf(v0 - m) + __expf(v1 - m);
#pragma unroll
    for (int o = 16; o > 0; o >>= 1) s += __shfl_xor_sync(0xffffffffu, s, o);
    float l = m + __logf(s);
    float* orow = out + (size_t)warp * 64;
    orow[lane] = v0 - l;
    orow[32 + lane] = v1 - l;
}

// ---------------- launch ----------------------------------------------------
extern "C" void kernel_launch(void* const* d_in, const int* in_sizes, int n_in,
                              void* d_out, int out_size) {
    const float* x  = (const float*)d_in[0];
    const int*   ei = (const int*)d_in[1];
    const float* W0 = (const float*)d_in[2];
    const float* b0 = (const float*)d_in[3];
    const float* W1 = (const float*)d_in[4];
    const float* b1 = (const float*)d_in[5];
    const float* W2 = (const float*)d_in[6];
    const float* b2 = (const float*)d_in[7];

    const int N = in_sizes[0] / FDIM;
    const int E = in_sizes[1] / 2;
    const int* src = ei;
    const int* dst = ei + E;

    float *h, *buf, *dis, *csr_norm;
    int *cnt, *rowptr, *cursor, *bsum, *csr_src;
    cudaGetSymbolAddress((void**)&h, g_h);
    cudaGetSymbolAddress((void**)&buf, g_buf);
    cudaGetSymbolAddress((void**)&dis, g_dis);
    cudaGetSymbolAddress((void**)&cnt, g_cnt);
    cudaGetSymbolAddress((void**)&rowptr, g_rowptr);
    cudaGetSymbolAddress((void**)&cursor, g_cursor);
    cudaGetSymbolAddress((void**)&bsum, g_bsum);
    cudaGetSymbolAddress((void**)&csr_src, g_csr_src);
    cudaGetSymbolAddress((void**)&csr_norm, g_csr_norm);

    // smem: 2*(BM*136) + 2*(128*(BN+8)) bf16 elements
    const int smemTC128 = (2 * 64 * 136 + 2 * 128 * 136) * 2;   // 104448
    const int smemTC64  = (2 * 128 * 136 + 2 * 128 * 72) * 2;   // 106496
    cudaFuncSetAttribute((const void*)gemm_tc_kernel<128, false>,
                         cudaFuncAttributeMaxDynamicSharedMemorySize, smemTC128);
    cudaFuncSetAttribute((const void*)gemm_tc_kernel<128, true>,
                         cudaFuncAttributeMaxDynamicSharedMemorySize, smemTC128);
    cudaFuncSetAttribute((const void*)gemm_tc_kernel<64, true>,
                         cudaFuncAttributeMaxDynamicSharedMemorySize, smemTC64);

    const int T = 256;
    auto cdiv = [](long long a, long long b) { return (unsigned)((a + b - 1) / b); };
    const int nb = (int)cdiv(N, SCAN_B);

    // ---- CSR build ----
    zero_cnt_kernel<<<cdiv(N, T), T>>>(cnt, N);
    hist_kernel<<<cdiv(E, T), T>>>(dst, cnt, E);
    dis_kernel<<<cdiv(N, T), T>>>(cnt, dis, N);
    scan1_kernel<<<nb, SCAN_B>>>(cnt, rowptr, bsum, N);
    scan2_kernel<<<1, SCAN_B>>>(bsum, nb);
    scan3_kernel<<<cdiv(N, T), T>>>(rowptr, cursor, bsum, N);
    permute_kernel<<<cdiv(E, T), T>>>(src, dst, dis, cursor, csr_src, csr_norm, E);

    const unsigned warp_grid = cdiv((long long)N * 32, T);

    // layer 0
    gemm_tc_kernel<128, false><<<cdiv(N, 64), T, smemTC128>>>(x, W0, h, N);
    agg_gather128_kernel<<<warp_grid, T>>>(h, rowptr, cnt, csr_src, csr_norm, b0, dis, buf, N);

    // layer 1 (relu fused into A-stage)
    gemm_tc_kernel<128, true><<<cdiv(N, 64), T, smemTC128>>>(buf, W1, h, N);
    agg_gather128_kernel<<<warp_grid, T>>>(h, rowptr, cnt, csr_src, csr_norm, b1, dis, buf, N);

    // layer 2 (64 out dims, BM=128)
    gemm_tc_kernel<64, true><<<cdiv(N, 128), T, smemTC64>>>(buf, W2, h, N);
    agg_gather64_kernel<<<warp_grid, T>>>(h, rowptr, cnt, csr_src, csr_norm, b2, dis, buf, N);

    // relu + log_softmax -> d_out
    final_kernel<<<warp_grid, T>>>(buf, (float*)d_out, N);
}

// round 7
// speedup vs baseline: 2.2555x; 1.0253x over previous
#include <cuda_runtime.h>
#include <cuda_bf16.h>
#include <cstdint>

#define N_NODES_MAX 100000
#define E_MAX       1600000
#define FDIM        128
#define SCAN_B      1024

// ---------------- scratch (device globals; no allocations allowed) ----------
__device__ float g_h[N_NODES_MAX * FDIM];    // GEMM output  (51.2 MB)
__device__ float g_buf[N_NODES_MAX * FDIM];  // aggregation output (51.2 MB)
__device__ float g_dis[N_NODES_MAX];         // rsqrt(deg)
__device__ int   g_cnt[N_NODES_MAX];         // in-degree (no self-loop)
__device__ int   g_rowptr[N_NODES_MAX];      // exclusive-scan of cnt
__device__ int   g_cursor[N_NODES_MAX];      // permute cursors
__device__ int   g_bsum[(N_NODES_MAX + SCAN_B - 1) / SCAN_B + 1];
__device__ int   g_csr_src[E_MAX];
__device__ float g_csr_norm[E_MAX];

// ---------------- CSR build --------------------------------------------------
__global__ void zero_cnt_kernel(int* cnt, int n) {
    int i = blockIdx.x * blockDim.x + threadIdx.x;
    if (i < n) cnt[i] = 0;
}

__global__ void hist_kernel(const int* __restrict__ dst, int* cnt, int E) {
    int e = blockIdx.x * blockDim.x + threadIdx.x;
    if (e < E) atomicAdd(&cnt[dst[e]], 1);
}

__global__ void dis_kernel(const int* __restrict__ cnt, float* dis, int n) {
    int i = blockIdx.x * blockDim.x + threadIdx.x;
    if (i < n) dis[i] = rsqrtf((float)(cnt[i] + 1));  // +1 self-loop
}

__global__ void scan1_kernel(const int* __restrict__ cnt, int* rowptr, int* bsum, int n) {
    __shared__ int sh[SCAN_B];
    int gid = blockIdx.x * SCAN_B + threadIdx.x;
    int v = (gid < n) ? cnt[gid] : 0;
    sh[threadIdx.x] = v;
    __syncthreads();
#pragma unroll
    for (int off = 1; off < SCAN_B; off <<= 1) {
        int t = (threadIdx.x >= off) ? sh[threadIdx.x - off] : 0;
        __syncthreads();
        sh[threadIdx.x] += t;
        __syncthreads();
    }
    if (gid < n) rowptr[gid] = sh[threadIdx.x] - v;  // exclusive
    if (threadIdx.x == SCAN_B - 1) bsum[blockIdx.x] = sh[SCAN_B - 1];
}

__global__ void scan2_kernel(int* bsum, int nb) {
    __shared__ int sh[SCAN_B];
    int v = (threadIdx.x < nb) ? bsum[threadIdx.x] : 0;
    sh[threadIdx.x] = v;
    __syncthreads();
#pragma unroll
    for (int off = 1; off < SCAN_B; off <<= 1) {
        int t = (threadIdx.x >= off) ? sh[threadIdx.x - off] : 0;
        __syncthreads();
        sh[threadIdx.x] += t;
        __syncthreads();
    }
    if (threadIdx.x < nb) bsum[threadIdx.x] = sh[threadIdx.x] - v;
}

__global__ void scan3_kernel(int* rowptr, int* cursor, const int* __restrict__ bsum, int n) {
    int gid = blockIdx.x * blockDim.x + threadIdx.x;
    if (gid < n) {
        int r = rowptr[gid] + bsum[gid / SCAN_B];
        rowptr[gid] = r;
        cursor[gid] = r;
    }
}

__global__ void permute_kernel(const int* __restrict__ src, const int* __restrict__ dst,
                               const float* __restrict__ dis, int* cursor,
                               int* csr_src, float* csr_norm, int E) {
    int e = blockIdx.x * blockDim.x + threadIdx.x;
    if (e < E) {
        int s = src[e], d = dst[e];
        int pos = atomicAdd(&cursor[d], 1);
        csr_src[pos] = s;
        csr_norm[pos] = dis[s] * dis[d];
    }
}

// ---------------- tensor-core GEMM (bf16x2 split, mma.sync) -----------------
__device__ __forceinline__ uint32_t pack_bf16x2(__nv_bfloat16 e0, __nv_bfloat16 e1) {
    return ((uint32_t)__bfloat16_as_ushort(e1) << 16) | (uint32_t)__bfloat16_as_ushort(e0);
}

__device__ __forceinline__ void split_store4(float4 v, __nv_bfloat16* ph, __nv_bfloat16* pl) {
    __nv_bfloat16 h0 = __float2bfloat16(v.x);
    __nv_bfloat16 h1 = __float2bfloat16(v.y);
    __nv_bfloat16 h2 = __float2bfloat16(v.z);
    __nv_bfloat16 h3 = __float2bfloat16(v.w);
    __nv_bfloat16 l0 = __float2bfloat16(v.x - __bfloat162float(h0));
    __nv_bfloat16 l1 = __float2bfloat16(v.y - __bfloat162float(h1));
    __nv_bfloat16 l2 = __float2bfloat16(v.z - __bfloat162float(h2));
    __nv_bfloat16 l3 = __float2bfloat16(v.w - __bfloat162float(h3));
    uint2 uh = make_uint2(pack_bf16x2(h0, h1), pack_bf16x2(h2, h3));
    uint2 ul = make_uint2(pack_bf16x2(l0, l1), pack_bf16x2(l2, l3));
    *reinterpret_cast<uint2*>(ph) = uh;
    *reinterpret_cast<uint2*>(pl) = ul;
}

#define MMA_BF16(acc, a, b)                                                              \
    asm volatile(                                                                        \
        "mma.sync.aligned.m16n8k16.row.col.f32.bf16.bf16.f32 "                           \
        "{%0,%1,%2,%3}, {%4,%5,%6,%7}, {%8,%9}, {%0,%1,%2,%3};"                          \
        : "+f"((acc)[0]), "+f"((acc)[1]), "+f"((acc)[2]), "+f"((acc)[3])                 \
        : "r"((a)[0]), "r"((a)[1]), "r"((a)[2]), "r"((a)[3]), "r"((b)[0]), "r"((b)[1]))

// out[M,BN] = (relu?)(A[M,128]) @ W[128,BN]; D = Ah@Wh + Ah@Wl + Al@Wh
template <int BN, bool RELU>
__global__ __launch_bounds__(256) void gemm_tc_kernel(const float* __restrict__ A,
                                                      const float* __restrict__ W,
                                                      float* __restrict__ out, int M) {
    constexpr int K = 128;
    constexpr int NWN = BN / 32;   // warps along N (4 or 2)
    constexpr int NWM = 8 / NWN;   // warps along M (2 or 4)
    constexpr int BM = NWM * 32;   // 64 or 128
    constexpr int KP = K + 8;      // A smem row stride (bf16)
    constexpr int NP = BN + 8;     // W smem row stride

    extern __shared__ __nv_bfloat16 smb[];
    __nv_bfloat16* Ah = smb;                 // [BM][KP]
    __nv_bfloat16* Al = Ah + BM * KP;
    __nv_bfloat16* Wh = Al + BM * KP;        // [K][NP]
    __nv_bfloat16* Wl = Wh + K * NP;

    const int t = threadIdx.x;
    const int block_row = blockIdx.x * BM;

    for (int i = t * 4; i < K * BN; i += 1024) {
        const int k = i / BN, n = i % BN;
        float4 v = *reinterpret_cast<const float4*>(W + i);
        split_store4(v, Wh + k * NP + n, Wl + k * NP + n);
    }
    for (int i = t * 4; i < BM * K; i += 1024) {
        const int r = i >> 7, c = i & 127;
        const int row = block_row + r;
        float4 v = make_float4(0.f, 0.f, 0.f, 0.f);
        if (row < M) v = *reinterpret_cast<const float4*>(A + (size_t)row * K + c);
        if (RELU) {
            v.x = fmaxf(v.x, 0.f); v.y = fmaxf(v.y, 0.f);
            v.z = fmaxf(v.z, 0.f); v.w = fmaxf(v.w, 0.f);
        }
        split_store4(v, Ah + r * KP + c, Al + r * KP + c);
    }
    __syncthreads();

    const int w = t >> 5, l = t & 31;
    const int wm = w / NWN, wn = w % NWN;   // warp tile = 32x32
    const int g = l >> 2, tq = l & 3;

    float acc[2][4][4];
#pragma unroll
    for (int mi = 0; mi < 2; mi++)
#pragma unroll
        for (int ni = 0; ni < 4; ni++)
#pragma unroll
            for (int r = 0; r < 4; r++) acc[mi][ni][r] = 0.f;

    const int a_row0 = wm * 32 + g;
    const int b_row  = l & 15;
    const int b_col  = wn * 32;

#pragma unroll
    for (int kk = 0; kk < 8; kk++) {
        const int k0 = kk * 16;
        uint32_t ah[2][4], al_[2][4];
#pragma unroll
        for (int mi = 0; mi < 2; mi++) {
            const int rb = (a_row0 + mi * 16) * KP + k0 + 2 * tq;
            ah[mi][0]  = *reinterpret_cast<const uint32_t*>(Ah + rb);
            ah[mi][1]  = *reinterpret_cast<const uint32_t*>(Ah + rb + 8 * KP);
            ah[mi][2]  = *reinterpret_cast<const uint32_t*>(Ah + rb + 8);
            ah[mi][3]  = *reinterpret_cast<const uint32_t*>(Ah + rb + 8 * KP + 8);
            al_[mi][0] = *reinterpret_cast<const uint32_t*>(Al + rb);
            al_[mi][1] = *reinterpret_cast<const uint32_t*>(Al + rb + 8 * KP);
            al_[mi][2] = *reinterpret_cast<const uint32_t*>(Al + rb + 8);
            al_[mi][3] = *reinterpret_cast<const uint32_t*>(Al + rb + 8 * KP + 8);
        }
        uint32_t bh[4][2], bl[4][2];
#pragma unroll
        for (int ni = 0; ni < 4; ni++) {
            const int off = (k0 + b_row) * NP + b_col + ni * 8;
            uint32_t ph = (uint32_t)__cvta_generic_to_shared(Wh + off);
            uint32_t pl = (uint32_t)__cvta_generic_to_shared(Wl + off);
            asm volatile("ldmatrix.sync.aligned.m8n8.x2.trans.shared.b16 {%0,%1}, [%2];"
                         : "=r"(bh[ni][0]), "=r"(bh[ni][1]) : "r"(ph));
            asm volatile("ldmatrix.sync.aligned.m8n8.x2.trans.shared.b16 {%0,%1}, [%2];"
                         : "=r"(bl[ni][0]), "=r"(bl[ni][1]) : "r"(pl));
        }
#pragma unroll
        for (int mi = 0; mi < 2; mi++)
#pragma unroll
            for (int ni = 0; ni < 4; ni++) {
                MMA_BF16(acc[mi][ni], ah[mi], bh[ni]);
                MMA_BF16(acc[mi][ni], ah[mi], bl[ni]);
                MMA_BF16(acc[mi][ni], al_[mi], bh[ni]);
            }
    }

#pragma unroll
    for (int mi = 0; mi < 2; mi++) {
#pragma unroll
        for (int ni = 0; ni < 4; ni++) {
            const int row = block_row + wm * 32 + mi * 16 + g;
            const int col = wn * 32 + ni * 8 + 2 * tq;
            if (row < M)
                *reinterpret_cast<float2*>(out + (size_t)row * BN + col) =
                    make_float2(acc[mi][ni][0], acc[mi][ni][1]);
            if (row + 8 < M)
                *reinterpret_cast<float2*>(out + (size_t)(row + 8) * BN + col) =
                    make_float2(acc[mi][ni][2], acc[mi][ni][3]);
        }
    }
}

// ---------------- aggregation: warp-per-node CSR gather ---------------------
__device__ __forceinline__ void stcs4(float* p, float4 v) {
    asm volatile("st.global.cs.v4.f32 [%0], {%1,%2,%3,%4};"
                 :: "l"(p), "f"(v.x), "f"(v.y), "f"(v.z), "f"(v.w) : "memory");
}
__device__ __forceinline__ void stcs2(float* p, float2 v) {
    asm volatile("st.global.cs.v2.f32 [%0], {%1,%2};"
                 :: "l"(p), "f"(v.x), "f"(v.y) : "memory");
}

__global__ void agg_gather128_kernel(const float* __restrict__ h,
                                     const int* __restrict__ rowptr,
                                     const int* __restrict__ cnt,
                                     const int* __restrict__ csr_src,
                                     const float* __restrict__ csr_norm,
                                     const float* __restrict__ b,
                                     const float* __restrict__ dis,
                                     float* __restrict__ out, int n) {
    int warp = (blockIdx.x * blockDim.x + threadIdx.x) >> 5;
    int lane = threadIdx.x & 31;
    if (warp >= n) return;
    const int v = warp;
    const int c = lane * 4;

    float d = dis[v];
    float sn = d * d;
    float4 acc = *reinterpret_cast<const float4*>(b + c);
    float4 hv = *reinterpret_cast<const float4*>(h + (size_t)v * 128 + c);
    acc.x += sn * hv.x; acc.y += sn * hv.y; acc.z += sn * hv.z; acc.w += sn * hv.w;

    int j = rowptr[v];
    const int end = j + cnt[v];
    for (; j + 8 <= end; j += 8) {
        int s[8]; float nn[8];
#pragma unroll
        for (int q = 0; q < 8; q++) { s[q] = __ldg(csr_src + j + q); nn[q] = __ldg(csr_norm + j + q); }
        float4 vv[8];
#pragma unroll
        for (int q = 0; q < 8; q++)
            vv[q] = *reinterpret_cast<const float4*>(h + (size_t)s[q] * 128 + c);
#pragma unroll
        for (int q = 0; q < 8; q++) {
            acc.x += nn[q] * vv[q].x; acc.y += nn[q] * vv[q].y;
            acc.z += nn[q] * vv[q].z; acc.w += nn[q] * vv[q].w;
        }
    }
    if (j + 4 <= end) {
        int s[4]; float nn[4];
#pragma unroll
        for (int q = 0; q < 4; q++) { s[q] = __ldg(csr_src + j + q); nn[q] = __ldg(csr_norm + j + q); }
        float4 vv[4];
#pragma unroll
        for (int q = 0; q < 4; q++)
            vv[q] = *reinterpret_cast<const float4*>(h + (size_t)s[q] * 128 + c);
#pragma unroll
        for (int q = 0; q < 4; q++) {
            acc.x += nn[q] * vv[q].x; acc.y += nn[q] * vv[q].y;
            acc.z += nn[q] * vv[q].z; acc.w += nn[q] * vv[q].w;
        }
        j += 4;
    }
    for (; j < end; ++j) {
        int s = __ldg(csr_src + j);
        float nn = __ldg(csr_norm + j);
        float4 vv = *reinterpret_cast<const float4*>(h + (size_t)s * 128 + c);
        acc.x += nn * vv.x; acc.y += nn * vv.y; acc.z += nn * vv.z; acc.w += nn * vv.w;
    }
    stcs4(out + (size_t)v * 128 + c, acc);
}

__global__ void agg_gather64_kernel(const float* __restrict__ h,
                                    const int* __restrict__ rowptr,
                                    const int* __restrict__ cnt,
                                    const int* __restrict__ csr_src,
                                    const float* __restrict__ csr_norm,
                                    const float* __restrict__ b,
                                    const float* __restrict__ dis,
                                    float* __restrict__ out, int n) {
    int warp = (blockIdx.x * blockDim.x + threadIdx.x) >> 5;
    int lane = threadIdx.x & 31;
    if (warp >= n) return;
    const int v = warp;
    const int c = lane * 2;

    float d = dis[v];
    float sn = d * d;
    float2 acc = *reinterpret_cast<const float2*>(b + c);
    float2 hv = *reinterpret_cast<const float2*>(h + (size_t)v * 64 + c);
    acc.x += sn * hv.x; acc.y += sn * hv.y;

    int j = rowptr[v];
    const int end = j + cnt[v];
    for (; j + 8 <= end; j += 8) {
        int s[8]; float nn[8];
#pragma unroll
        for (int q = 0; q < 8; q++) { s[q] = __ldg(csr_src + j + q); nn[q] = __ldg(csr_norm + j + q); }
        float2 vv[8];
#pragma unroll
        for (int q = 0; q < 8; q++)
            vv[q] = *reinterpret_cast<const float2*>(h + (size_t)s[q] * 64 + c);
#pragma unroll
        for (int q = 0; q < 8; q++) { acc.x += nn[q] * vv[q].x; acc.y += nn[q] * vv[q].y; }
    }
    for (; j < end; ++j) {
        int s = __ldg(csr_src + j);
        float nn = __ldg(csr_norm + j);
        float2 vv = *reinterpret_cast<const float2*>(h + (size_t)s * 64 + c);
        acc.x += nn * vv.x; acc.y += nn * vv.y;
    }
    stcs2(out + (size_t)v * 64 + c, acc);
}

// ---------------- epilogue: relu + log_softmax over 64 cols (stride 64) -----
__global__ void final_kernel(const float* __restrict__ hin, float* __restrict__ out, int n) {
    int warp = (blockIdx.x * blockDim.x + threadIdx.x) >> 5;
    int lane = threadIdx.x & 31;
    if (warp >= n) return;
    const float* row = hin + (size_t)warp * 64;
    float v0 = fmaxf(row[lane], 0.f);
    float v1 = fmaxf(row[32 + lane], 0.f);
    float m = fmaxf(v0, v1);
#pragma unroll
    for (int o = 16; o > 0; o >>= 1) m = fmaxf(m, __shfl_xor_sync(0xffffffffu, m, o));
    float s = __expf(v0 - m) + __expf(v1 - m);
#pragma unroll
    for (int o = 16; o > 0; o >>= 1) s += __shfl_xor_sync(0xffffffffu, s, o);
    float l = m + __logf(s);
    float* orow = out + (size_t)warp * 64;
    orow[lane] = v0 - l;
    orow[32 + lane] = v1 - l;
}

// ---------------- launch ----------------------------------------------------
extern "C" void kernel_launch(void* const* d_in, const int* in_sizes, int n_in,
                              void* d_out, int out_size) {
    const float* x  = (const float*)d_in[0];
    const int*   ei = (const int*)d_in[1];
    const float* W0 = (const float*)d_in[2];
    const float* b0 = (const float*)d_in[3];
    const float* W1 = (const float*)d_in[4];
    const float* b1 = (const float*)d_in[5];
    const float* W2 = (const float*)d_in[6];
    const float* b2 = (const float*)d_in[7];

    const int N = in_sizes[0] / FDIM;
    const int E = in_sizes[1] / 2;
    const int* src = ei;
    const int* dst = ei + E;

    float *h, *buf, *dis, *csr_norm;
    int *cnt, *rowptr, *cursor, *bsum, *csr_src;
    cudaGetSymbolAddress((void**)&h, g_h);
    cudaGetSymbolAddress((void**)&buf, g_buf);
    cudaGetSymbolAddress((void**)&dis, g_dis);
    cudaGetSymbolAddress((void**)&cnt, g_cnt);
    cudaGetSymbolAddress((void**)&rowptr, g_rowptr);
    cudaGetSymbolAddress((void**)&cursor, g_cursor);
    cudaGetSymbolAddress((void**)&bsum, g_bsum);
    cudaGetSymbolAddress((void**)&csr_src, g_csr_src);
    cudaGetSymbolAddress((void**)&csr_norm, g_csr_norm);

    const int smemTC128 = (2 * 64 * 136 + 2 * 128 * 136) * 2;   // 104448
    const int smemTC64  = (2 * 128 * 136 + 2 * 128 * 72) * 2;   // 106496
    cudaFuncSetAttribute((const void*)gemm_tc_kernel<128, false>,
                         cudaFuncAttributeMaxDynamicSharedMemorySize, smemTC128);
    cudaFuncSetAttribute((const void*)gemm_tc_kernel<128, true>,
                         cudaFuncAttributeMaxDynamicSharedMemorySize, smemTC128);
    cudaFuncSetAttribute((const void*)gemm_tc_kernel<64, true>,
                         cudaFuncAttributeMaxDynamicSharedMemorySize, smemTC64);

    // side stream + events, created once on the (uncaptured) correctness call
    static cudaStream_t s2 = nullptr;
    static cudaEvent_t evFork = nullptr, evJoin = nullptr;
    if (s2 == nullptr) {
        cudaStreamCreate(&s2);
        cudaEventCreateWithFlags(&evFork, cudaEventDisableTiming);
        cudaEventCreateWithFlags(&evJoin, cudaEventDisableTiming);
    }

    const int T = 256;
    auto cdiv = [](long long a, long long b) { return (unsigned)((a + b - 1) / b); };
    const int nb = (int)cdiv(N, SCAN_B);

    // ---- fork: CSR build on s2, GEMM-0 on main stream ----
    cudaEventRecord(evFork, 0);
    cudaStreamWaitEvent(s2, evFork, 0);

    zero_cnt_kernel<<<cdiv(N, T), T, 0, s2>>>(cnt, N);
    hist_kernel<<<cdiv(E, T), T, 0, s2>>>(dst, cnt, E);
    dis_kernel<<<cdiv(N, T), T, 0, s2>>>(cnt, dis, N);
    scan1_kernel<<<nb, SCAN_B, 0, s2>>>(cnt, rowptr, bsum, N);
    scan2_kernel<<<1, SCAN_B, 0, s2>>>(bsum, nb);
    scan3_kernel<<<cdiv(N, T), T, 0, s2>>>(rowptr, cursor, bsum, N);
    permute_kernel<<<cdiv(E, T), T, 0, s2>>>(src, dst, dis, cursor, csr_src, csr_norm, E);
    cudaEventRecord(evJoin, s2);

    gemm_tc_kernel<128, false><<<cdiv(N, 64), T, smemTC128>>>(x, W0, h, N);

    cudaStreamWaitEvent(0, evJoin, 0);  // join before first gather

    const unsigned warp_grid = cdiv((long long)N * 32, T);

    // layer 0 aggregation
    agg_gather128_kernel<<<warp_grid, T>>>(h, rowptr, cnt, csr_src, csr_norm, b0, dis, buf, N);

    // layer 1
    gemm_tc_kernel<128, true><<<cdiv(N, 64), T, smemTC128>>>(buf, W1, h, N);
    agg_gather128_kernel<<<warp_grid, T>>>(h, rowptr, cnt, csr_src, csr_norm, b1, dis, buf, N);

    // layer 2 (64 out dims, BM=128)
    gemm_tc_kernel<64, true><<<cdiv(N, 128), T, smemTC64>>>(buf, W2, h, N);
    agg_gather64_kernel<<<warp_grid, T>>>(h, rowptr, cnt, csr_src, csr_norm, b2, dis, buf, N);

    // relu + log_softmax -> d_out
    final_kernel<<<warp_grid, T>>>(buf, (float*)d_out, N);
}